// round 11
// baseline (speedup 1.0000x reference)
#include <cuda_runtime.h>
#include <cuda_bf16.h>
#include <cstdint>
#include <cstddef>

#define T_STEPS 512
#define B_SZ    256
#define NO_SZ   128

// ---------------------------------------------------------------------------
// Static scratch.
//   g_G   [tile][b][r]   fp32 preacts (gsum folds sources j>=c+2 in place)
//   g_Hep [tile][b][k]   fp32 hidden epochs
//   g_R   [tile][b][o]   prefix-summed output projections
//   g_C   [ctile][b][r]  off-diagonal recurrent projections (z <= j-2 only)
// ---------------------------------------------------------------------------
__device__ float g_G  [1020u * 64  * 256];
__device__ float g_Hep[1020u * 64  * 256];
__device__ float g_R  [1020u * 128 * 256];
__device__ float g_C  [988u  * 64  * 256];

__device__ __constant__ int c_S[8] = {0, 0, 256, 512, 704, 832, 912, 960};

__device__ __forceinline__ int hb(int j) { return 1024 - (1024 >> j); }

__device__ __forceinline__ float ftanh(float x) {
    float t = __expf(2.0f * x);
    return 1.0f - __fdividef(2.0f, t + 1.0f);
}

// ---------------------------------------------------------------------------
// bf16 MMA m16n8k16 (row.col, f32 accum)
// ---------------------------------------------------------------------------
__device__ __forceinline__ void mma_bf16(float* d, const uint32_t* a, const uint32_t* b)
{
    asm volatile(
        "mma.sync.aligned.m16n8k16.row.col.f32.bf16.bf16.f32 "
        "{%0,%1,%2,%3},{%4,%5,%6,%7},{%8,%9},{%0,%1,%2,%3};\n"
        : "+f"(d[0]), "+f"(d[1]), "+f"(d[2]), "+f"(d[3])
        : "r"(a[0]), "r"(a[1]), "r"(a[2]), "r"(a[3]), "r"(b[0]), "r"(b[1]));
}

__device__ __forceinline__ uint32_t pack2(float x0, float x1, bool lo)
{
    __nv_bfloat16 h0 = __float2bfloat16(x0);
    __nv_bfloat16 h1 = __float2bfloat16(x1);
    if (lo) {
        h0 = __float2bfloat16(x0 - __bfloat162float(h0));
        h1 = __float2bfloat16(x1 - __bfloat162float(h1));
    }
    __nv_bfloat162 p = __halves2bfloat162(h0, h1);
    return *reinterpret_cast<uint32_t*>(&p);
}

// Shared layout (uint32 words), total 9216 words = 36864 B:
//   AH [64][36] @0   AL [64][36] @2304   BH [64][36] @4608   BL [64][36] @6912
//   S  (float [64][68]) overlays BH/BL region
#define AH_OFF 0
#define AL_OFF 2304
#define BH_OFF 4608
#define BL_OFF 6912

// Stage A (64 rows x 64 k, row-major lda) and B (64 cols x 64 k, k-contig ldb).
// koff applies to BOTH A and B k-indices; pass base (unoffset) pointers.
__device__ __forceinline__ void stage_AB(uint32_t* su,
                                         const float* __restrict__ Ag, int lda, int koff,
                                         const float* __restrict__ Bg, int ldb,
                                         int tid)
{
    for (int idx = tid; idx < 64 * 32; idx += 256) {
        int r = idx >> 5, p = idx & 31;
        float x0 = Ag[(size_t)r * lda + koff + 2 * p];
        float x1 = Ag[(size_t)r * lda + koff + 2 * p + 1];
        su[AH_OFF + r * 36 + p] = pack2(x0, x1, false);
        su[AL_OFF + r * 36 + p] = pack2(x0, x1, true);
    }
    for (int idx = tid; idx < 64 * 16; idx += 256) {
        int c = idx >> 4, q = idx & 15;
        float4 v = *(const float4*)&Bg[(size_t)c * ldb + koff + 4 * q];
        su[BH_OFF + c * 36 + 2 * q]     = pack2(v.x, v.y, false);
        su[BL_OFF + c * 36 + 2 * q]     = pack2(v.x, v.y, true);
        su[BH_OFF + c * 36 + 2 * q + 1] = pack2(v.z, v.w, false);
        su[BL_OFF + c * 36 + 2 * q + 1] = pack2(v.z, v.w, true);
    }
}

// 64x64 tile MMA: warp w -> rows (w&3)*16.., cols (w>>2)*32..; acc[4][4]
__device__ __forceinline__ void mma_block(const uint32_t* su, int warp, int lane,
                                          float (&acc)[4][4])
{
    const int mrow = (warp & 3) * 16;
    const int nb   = (warp >> 2) * 32;
    const int gr   = lane >> 2, tg = lane & 3;
#pragma unroll
    for (int c = 0; c < 4; c++) {
        const int pb = c * 8;
        uint32_t ah[4], al[4];
        ah[0] = su[AH_OFF + (mrow + gr)     * 36 + pb + tg];
        ah[1] = su[AH_OFF + (mrow + gr + 8) * 36 + pb + tg];
        ah[2] = su[AH_OFF + (mrow + gr)     * 36 + pb + 4 + tg];
        ah[3] = su[AH_OFF + (mrow + gr + 8) * 36 + pb + 4 + tg];
        al[0] = su[AL_OFF + (mrow + gr)     * 36 + pb + tg];
        al[1] = su[AL_OFF + (mrow + gr + 8) * 36 + pb + tg];
        al[2] = su[AL_OFF + (mrow + gr)     * 36 + pb + 4 + tg];
        al[3] = su[AL_OFF + (mrow + gr + 8) * 36 + pb + 4 + tg];
#pragma unroll
        for (int nt = 0; nt < 4; nt++) {
            const int colb = nb + nt * 8 + gr;
            uint32_t bh[2], bl[2];
            bh[0] = su[BH_OFF + colb * 36 + pb + tg];
            bh[1] = su[BH_OFF + colb * 36 + pb + 4 + tg];
            bl[0] = su[BL_OFF + colb * 36 + pb + tg];
            bl[1] = su[BL_OFF + colb * 36 + pb + 4 + tg];
            mma_bf16(acc[nt], ah, bh);
            mma_bf16(acc[nt], ah, bl);
            mma_bf16(acc[nt], al, bh);
        }
    }
}

// acc -> S[col][row] transpose staging (S overlays B smem region)
__device__ __forceinline__ void acc_to_S(float* Sf, int warp, int lane, float (&acc)[4][4])
{
    const int mrow = (warp & 3) * 16;
    const int nb   = (warp >> 2) * 32;
    const int gr   = lane >> 2, tg = lane & 3;
#pragma unroll
    for (int nt = 0; nt < 4; nt++) {
        const int c0 = nb + nt * 8 + 2 * tg;
        Sf[(size_t)c0       * 68 + mrow + gr]     = acc[nt][0];
        Sf[(size_t)(c0 + 1) * 68 + mrow + gr]     = acc[nt][1];
        Sf[(size_t)c0       * 68 + mrow + gr + 8] = acc[nt][2];
        Sf[(size_t)(c0 + 1) * 68 + mrow + gr + 8] = acc[nt][3];
    }
}

// ---------------------------------------------------------------------------
// g0: G[c][m] = Wi_c @ x_{m<<c} + (Wi_bias + Wh_bias).
// grid (ntiles, 4), 256 thr; tile index = idx0 + blockIdx.x.
// ---------------------------------------------------------------------------
__global__ void __launch_bounds__(256) g0_kernel(const float* __restrict__ X,
                                                 const float* __restrict__ Wi,
                                                 const float* __restrict__ Wh,
                                                 int idx0)
{
    __shared__ __align__(16) uint32_t su[9216];
    float* Sf = (float*)(su + BH_OFF);

    const int idx = idx0 + blockIdx.x;
    const int v   = 1024 - idx;
    const int c   = __clz(v - 1) - 22;
    const int m   = idx - (1024 - (1024 >> c));
    const int t   = m << c;
    const int b0  = blockIdx.y * 64;
    const int tid = threadIdx.x;
    const int warp = tid >> 5, lane = tid & 31;

    const float* Ag = Wi + (size_t)(c * 64) * 129;
    const float* Bg = X + ((size_t)t * 256 + b0) * 128;

    float acc[4][4];
#pragma unroll
    for (int q = 0; q < 4; q++)
#pragma unroll
        for (int u = 0; u < 4; u++) acc[q][u] = 0.f;

    for (int kh = 0; kh < 2; kh++) {
        stage_AB(su, Ag, 129, kh * 64, Bg, 128, tid);
        __syncthreads();
        mma_block(su, warp, lane, acc);
        __syncthreads();
    }

    {
        const int mrow = (warp & 3) * 16, gr = lane >> 2;
        int r0 = c * 64 + mrow + gr, r1 = r0 + 8;
        float ba = Wi[(size_t)r0 * 129 + 128] + Wh[(size_t)r0 * 513 + 512];
        float bb = Wi[(size_t)r1 * 129 + 128] + Wh[(size_t)r1 * 513 + 512];
#pragma unroll
        for (int nt = 0; nt < 4; nt++) {
            acc[nt][0] += ba; acc[nt][1] += ba;
            acc[nt][2] += bb; acc[nt][3] += bb;
        }
    }

    acc_to_S(Sf, warp, lane, acc);
    __syncthreads();

    float* out = g_G + (size_t)idx * 16384 + (size_t)b0 * 64;
    for (int i = tid; i < 64 * 16; i += 256) {
        int col = i >> 4, rq = i & 15;
        *(float4*)&out[(size_t)col * 64 + rq * 4] = *(float4*)&Sf[(size_t)col * 68 + rq * 4];
    }
}

// ---------------------------------------------------------------------------
// projC (deferred only): C[z][j][e] = Wh[z-rows, j-cols] @ H_j[e],  z <= j-2.
// grid (U_j, 4, j-1), 256 threads.
// ---------------------------------------------------------------------------
__global__ void __launch_bounds__(256) projC_kernel(const float* __restrict__ Wh, int j)
{
    __shared__ __align__(16) uint32_t su[9216];
    float* Sf = (float*)(su + BH_OFF);

    const int e   = blockIdx.x;
    const int U   = gridDim.x;
    const int b0  = blockIdx.y * 64;
    const int z   = blockIdx.z;
    const int tid = threadIdx.x;
    const int warp = tid >> 5, lane = tid & 31;

    const float* Ag = Wh + (size_t)(z * 64) * 513 + j * 64;
    const float* Bg = g_Hep + (size_t)(hb(j) + e) * 16384 + (size_t)b0 * 64;

    float acc[4][4];
#pragma unroll
    for (int q = 0; q < 4; q++)
#pragma unroll
        for (int u = 0; u < 4; u++) acc[q][u] = 0.f;

    stage_AB(su, Ag, 513, 0, Bg, 64, tid);
    __syncthreads();
    mma_block(su, warp, lane, acc);
    __syncthreads();
    acc_to_S(Sf, warp, lane, acc);
    __syncthreads();

    float* out = g_C + (size_t)(c_S[j] + z * U + e) * 16384 + (size_t)b0 * 64;
    for (int i = tid; i < 64 * 16; i += 256) {
        int col = i >> 4, rq = i & 15;
        *(float4*)&out[(size_t)col * 64 + rq * 4] =
            *(float4*)&Sf[(size_t)col * 68 + rq * 4];
    }
}

// ---------------------------------------------------------------------------
// gsum: G'[m] = G[m] + sum_{j >= C+2} C[C][j][(m-1)>>(j-C)]   (m >= 1)
// ---------------------------------------------------------------------------
__global__ void __launch_bounds__(256) gsum_kernel(int C)
{
    const int m   = blockIdx.x + 1;
    const int b0  = blockIdx.y * 64;
    const int tid = threadIdx.x;
    const int HB  = 1024 - (1024 >> C);

    float* Gt = g_G + (size_t)(HB + m) * 16384 + (size_t)b0 * 64;

    const float* Ct[6];
    int ns = 0;
    for (int j = C + 2; j < 8; j++) {
        int e = (m - 1) >> (j - C);
        Ct[ns++] = g_C + (size_t)(c_S[j] + C * (512 >> j) + e) * 16384 + (size_t)b0 * 64;
    }

    for (int i = tid; i < 1024; i += 256) {
        float4 a = *(float4*)&Gt[i * 4];
        for (int s = 0; s < ns; s++) {
            float4 v = *(const float4*)&Ct[s][i * 4];
            a.x += v.x; a.y += v.y; a.z += v.z; a.w += v.w;
        }
        *(float4*)&Gt[i * 4] = a;
    }
}

// ---------------------------------------------------------------------------
// projR: R_j[e] rows z*64.. = Wo[rows, j-cols] @ H_j[e] + R_{j+1}[e>>1]
//        (+Wo bias at j=7; tanh->Y at j=0).
// ---------------------------------------------------------------------------
__global__ void __launch_bounds__(256) projR_kernel(const float* __restrict__ Wo,
                                                    float* __restrict__ Y, int j)
{
    __shared__ __align__(16) uint32_t su[9216];
    float* Sf = (float*)(su + BH_OFF);

    const int e   = blockIdx.x;
    const int b0  = blockIdx.y * 64;
    const int z   = blockIdx.z;
    const int tid = threadIdx.x;
    const int warp = tid >> 5, lane = tid & 31;

    const float* Ag = Wo + (size_t)(z * 64) * 513 + j * 64;
    const float* Bg = g_Hep + (size_t)(hb(j) + e) * 16384 + (size_t)b0 * 64;

    float acc[4][4];
#pragma unroll
    for (int q = 0; q < 4; q++)
#pragma unroll
        for (int u = 0; u < 4; u++) acc[q][u] = 0.f;

    stage_AB(su, Ag, 513, 0, Bg, 64, tid);
    __syncthreads();
    mma_block(su, warp, lane, acc);
    __syncthreads();
    acc_to_S(Sf, warp, lane, acc);
    __syncthreads();

    const int o0 = z * 64;
    const float* Rpar = (j < 7)
        ? g_R + (size_t)(hb(j + 1) + (e >> 1)) * 32768
        : nullptr;
    for (int i = tid; i < 64 * 16; i += 256) {
        int col = i >> 4, rq = i & 15;
        float4 s = *(float4*)&Sf[(size_t)col * 68 + rq * 4];
        if (j < 7) {
            float4 p = *(const float4*)&Rpar[(size_t)(b0 + col) * 128 + o0 + rq * 4];
            s.x += p.x; s.y += p.y; s.z += p.z; s.w += p.w;
        } else {
            s.x += Wo[(size_t)(o0 + rq * 4 + 0) * 513 + 512];
            s.y += Wo[(size_t)(o0 + rq * 4 + 1) * 513 + 512];
            s.z += Wo[(size_t)(o0 + rq * 4 + 2) * 513 + 512];
            s.w += Wo[(size_t)(o0 + rq * 4 + 3) * 513 + 512];
        }
        if (j == 0) {
            float4 y = make_float4(ftanh(s.x), ftanh(s.y), ftanh(s.z), ftanh(s.w));
            *(float4*)&Y[((size_t)e * 256 + b0 + col) * 128 + o0 + rq * 4] = y;
        } else {
            *(float4*)&g_R[(size_t)(hb(j) + e) * 32768 +
                           (size_t)(b0 + col) * 128 + o0 + rq * 4] = s;
        }
    }
}

// ---------------------------------------------------------------------------
// seq<C>: H[m] = tanh(G'[m] + Wh[C,C+1]@H_{C+1}[(m-1)>>1] + W_CC @ H[m-1])
// The C+1-source product is computed JIT: its weights live in registers,
// the H_{C+1}[e] vector is prefetched (LDG 3 steps early, STS 2 steps early)
// into a parity-double-buffered SMEM slot, and the 64-FFMA dot runs on odd
// steps only.  Sources j>=C+2 are pre-folded into G by gsum.
// grid 128 CTAs x 2 batch cols, 128 threads; G prefetch depth 8.
// ---------------------------------------------------------------------------
template <int C>
__global__ void __launch_bounds__(128) seq_kernel(const float* __restrict__ Wh)
{
    constexpr int  U    = 512 >> C;
    constexpr bool HASC = (C < 7);
    constexpr int  HB   = 1024 - (1024 >> C);
    constexpr int  HBS  = (C < 7) ? (1024 - (1024 >> (C + 1))) : 0;
    constexpr int  U2   = U / 2;                  // epochs of source C+1
    constexpr int  D    = (U < 8) ? U : 8;

    const int tid = threadIdx.x;
    const int lb  = tid >> 6;
    const int r   = tid & 63;
    const int b   = blockIdx.x * 2 + lb;
    const int off = b * 64 + r;

    __shared__ float Ws [64][65];
    __shared__ float Ws1[64][65];
    __shared__ float Hs [2][2][64];
    __shared__ float Hst[2][2][64];   // [epoch parity][col][k]

    for (int i = tid; i < 4096; i += 128) {
        int rr = i >> 6, kk = i & 63;
        Ws[rr][kk] = Wh[(size_t)(C * 64 + rr) * 513 + C * 64 + kk];
        if (HASC)
            Ws1[rr][kk] = Wh[(size_t)(C * 64 + rr) * 513 + (C + 1) * 64 + kk];
    }

    const float* Gb  = g_G   + (size_t)HB  * 16384;
    const float* Sb  = g_Hep + (size_t)HBS * 16384;
    float*       Hbp = g_Hep + (size_t)HB  * 16384;

    float hfe[2] = {0.f, 0.f};
    if (HASC) {
        Hst[0][lb][r] = Sb[off];                            // e = 0
        if (U2 > 1) hfe[1] = Sb[(size_t)16384 + off];       // e = 1
    }

    float gv[D];
#pragma unroll
    for (int i = 0; i < D; i++)
        gv[i] = Gb[(size_t)i * 16384 + off];

    __syncthreads();

    float w[64], w1[64];
#pragma unroll
    for (int q = 0; q < 64; q++) {
        w[q] = Ws[r][q];
        if (HASC) w1[q] = Ws1[r][q];
    }

    float c1 = 0.f;

    for (int m0 = 0; m0 < U; m0 += D) {
#pragma unroll
        for (int i = 0; i < D; i++) {
            const int m  = m0 + i;
            const int rb = m & 1;
            float a = gv[i];
            if (m > 0) {
                if (HASC && (m & 1)) {
                    const int e = (m - 1) >> 1;
                    float c0 = 0.f, ca = 0.f, cb = 0.f, cc = 0.f;
#pragma unroll
                    for (int q = 0; q < 64; q += 4) {
                        float4 hv = *(const float4*)&Hst[e & 1][lb][q];
                        c0 += w1[q + 0] * hv.x;
                        ca += w1[q + 1] * hv.y;
                        cb += w1[q + 2] * hv.z;
                        cc += w1[q + 3] * hv.w;
                    }
                    c1 = (c0 + ca) + (cb + cc);
                }
                float a0 = 0.f, a1 = 0.f, a2 = 0.f, a3 = 0.f;
#pragma unroll
                for (int q = 0; q < 64; q += 4) {
                    float4 hv = *(const float4*)&Hs[rb][lb][q];
                    a0 += w[q + 0] * hv.x;
                    a1 += w[q + 1] * hv.y;
                    a2 += w[q + 2] * hv.z;
                    a3 += w[q + 3] * hv.w;
                }
                a += (a0 + a1) + (a2 + a3);
                if (HASC) a += c1;
            }
            float h = ftanh(a);
            Hbp[(size_t)m * 16384 + off] = h;
            Hs[rb ^ 1][lb][r] = h;
            if (HASC) {
                if ((m & 1) == 0) {                    // LDG for e = m/2 + 2
                    const int en = (m >> 1) + 2;
                    if (en < U2) hfe[en & 1] = Sb[(size_t)en * 16384 + off];
                } else {                               // STS for e = (m+1)/2
                    const int es = (m + 1) >> 1;
                    if (es < U2) Hst[es & 1][lb][r] = hfe[es & 1];
                }
            }
            if (m + D < U) gv[i] = Gb[(size_t)(m + D) * 16384 + off];
            __syncthreads();
        }
    }
}

// ---------------------------------------------------------------------------
// final H: out[T*B*NO + (j*64+r)*256 + b] = H_j[last epoch][b][r] (transpose)
// ---------------------------------------------------------------------------
__global__ void __launch_bounds__(256) finalH_kernel(float* __restrict__ out)
{
    __shared__ float S[64][65];
    const int j   = blockIdx.x;
    const int b0  = blockIdx.y * 64;
    const int tid = threadIdx.x;
    const int e   = (512 >> j) - 1;
    const float* Hj = g_Hep + (size_t)(hb(j) + e) * 16384;

    for (int i = tid; i < 4096; i += 256) {
        int rr = i & 63, bb = i >> 6;
        S[bb][rr] = Hj[(size_t)(b0 + bb) * 64 + rr];
    }
    __syncthreads();
    for (int i = tid; i < 4096; i += 256) {
        int bb = i & 63, rr = i >> 6;
        out[(size_t)T_STEPS * B_SZ * NO_SZ + (size_t)(j * 64 + rr) * 256 + b0 + bb] =
            S[bb][rr];
    }
}

// ---------------------------------------------------------------------------
// Launch.
//   main: g0_hi -> seq<7..0> (urgent projC eliminated: C1 is JIT inside seq)
//   s1  : g0_lo (levels 3..0)
//   s2  : projR chain (R_7..R_0 -> Y), join at end
//   s3  : projC deferred (z<=j-2) + gsum<C>; seq<C> gates on evGS[C]
// ---------------------------------------------------------------------------
static cudaStream_t s_s1 = nullptr, s_s2 = nullptr, s_s3 = nullptr;
static cudaEvent_t  s_ev0, s_evG0, s_evH[8], s_evR0, s_evGS[6];
static int s_state = 0;

static bool ensure_streams()
{
    if (s_state) return s_state > 0;
    bool ok = true;
    ok &= cudaStreamCreateWithFlags(&s_s1, cudaStreamNonBlocking) == cudaSuccess;
    ok &= cudaStreamCreateWithFlags(&s_s2, cudaStreamNonBlocking) == cudaSuccess;
    ok &= cudaStreamCreateWithFlags(&s_s3, cudaStreamNonBlocking) == cudaSuccess;
    ok &= cudaEventCreateWithFlags(&s_ev0,  cudaEventDisableTiming) == cudaSuccess;
    ok &= cudaEventCreateWithFlags(&s_evG0, cudaEventDisableTiming) == cudaSuccess;
    ok &= cudaEventCreateWithFlags(&s_evR0, cudaEventDisableTiming) == cudaSuccess;
    for (int i = 0; i < 8; i++)
        ok &= cudaEventCreateWithFlags(&s_evH[i], cudaEventDisableTiming) == cudaSuccess;
    for (int i = 0; i < 6; i++)
        ok &= cudaEventCreateWithFlags(&s_evGS[i], cudaEventDisableTiming) == cudaSuccess;
    s_state = ok ? 1 : -1;
    return ok;
}

extern "C" void kernel_launch(void* const* d_in, const int* in_sizes, int n_in,
                              void* d_out, int out_size)
{
    const float* X  = nullptr;
    const float* Wi = nullptr;
    const float* Wh = nullptr;
    const float* Wo = nullptr;
    for (int i = 0; i < n_in; i++) {
        switch (in_sizes[i]) {
            case 512 * 256 * 128: X  = (const float*)d_in[i]; break;
            case 512 * 129:       Wi = (const float*)d_in[i]; break;
            case 512 * 513:       Wh = (const float*)d_in[i]; break;
            case 128 * 513:       Wo = (const float*)d_in[i]; break;
            default: break;
        }
    }
    float* out = (float*)d_out;

    if (!ensure_streams()) {
        // -------- Fallback: single-stream chain ----------------------------
        g0_kernel<<<dim3(1020, 4), 256>>>(X, Wi, Wh, 0);
        seq_kernel<7><<<128, 128>>>(Wh);
        projR_kernel<<<dim3(4, 4, 2), 256>>>(Wo, out, 7);
        projC_kernel<<<dim3(4, 4, 6), 256>>>(Wh, 7);
        seq_kernel<6><<<128, 128>>>(Wh);
        projR_kernel<<<dim3(8, 4, 2), 256>>>(Wo, out, 6);
        projC_kernel<<<dim3(8, 4, 5), 256>>>(Wh, 6);
        gsum_kernel<<<dim3(15, 4), 256>>>(5);
        seq_kernel<5><<<128, 128>>>(Wh);
        projR_kernel<<<dim3(16, 4, 2), 256>>>(Wo, out, 5);
        projC_kernel<<<dim3(16, 4, 4), 256>>>(Wh, 5);
        gsum_kernel<<<dim3(31, 4), 256>>>(4);
        seq_kernel<4><<<128, 128>>>(Wh);
        projR_kernel<<<dim3(32, 4, 2), 256>>>(Wo, out, 4);
        projC_kernel<<<dim3(32, 4, 3), 256>>>(Wh, 4);
        gsum_kernel<<<dim3(63, 4), 256>>>(3);
        seq_kernel<3><<<128, 128>>>(Wh);
        projR_kernel<<<dim3(64, 4, 2), 256>>>(Wo, out, 3);
        projC_kernel<<<dim3(64, 4, 2), 256>>>(Wh, 3);
        gsum_kernel<<<dim3(127, 4), 256>>>(2);
        seq_kernel<2><<<128, 128>>>(Wh);
        projR_kernel<<<dim3(128, 4, 2), 256>>>(Wo, out, 2);
        projC_kernel<<<dim3(128, 4, 1), 256>>>(Wh, 2);
        gsum_kernel<<<dim3(255, 4), 256>>>(1);
        seq_kernel<1><<<128, 128>>>(Wh);
        projR_kernel<<<dim3(256, 4, 2), 256>>>(Wo, out, 1);
        gsum_kernel<<<dim3(511, 4), 256>>>(0);
        seq_kernel<0><<<128, 128>>>(Wh);
        projR_kernel<<<dim3(512, 4, 2), 256>>>(Wo, out, 0);
        finalH_kernel<<<dim3(8, 4), 256>>>(out);
        return;
    }

    cudaStream_t s1 = s_s1, s2 = s_s2, s3 = s_s3;

    // Fork: g0_lo (levels 3..0, tiles 0..959) on s1.
    cudaEventRecord(s_ev0, 0);
    cudaStreamWaitEvent(s1, s_ev0, 0);
    g0_kernel<<<dim3(960, 4), 256, 0, s1>>>(X, Wi, Wh, 0);
    cudaEventRecord(s_evG0, s1);

    // Main: g0_hi (levels 7..4, tiles 960..1019).
    g0_kernel<<<dim3(60, 4), 256>>>(X, Wi, Wh, 960);

    // ---- level 7 ----
    seq_kernel<7><<<128, 128>>>(Wh);
    cudaEventRecord(s_evH[7], 0);
    cudaStreamWaitEvent(s2, s_evH[7], 0);
    projR_kernel<<<dim3(4, 4, 2), 256, 0, s2>>>(Wo, out, 7);
    cudaStreamWaitEvent(s3, s_evH[7], 0);
    projC_kernel<<<dim3(4, 4, 6), 256, 0, s3>>>(Wh, 7);     // z=0..5
    gsum_kernel<<<dim3(15, 4), 256, 0, s3>>>(5);
    cudaEventRecord(s_evGS[5], s3);

    // ---- level 6 ----
    seq_kernel<6><<<128, 128>>>(Wh);
    cudaEventRecord(s_evH[6], 0);
    cudaStreamWaitEvent(s2, s_evH[6], 0);
    projR_kernel<<<dim3(8, 4, 2), 256, 0, s2>>>(Wo, out, 6);
    cudaStreamWaitEvent(s3, s_evH[6], 0);
    projC_kernel<<<dim3(8, 4, 5), 256, 0, s3>>>(Wh, 6);     // z=0..4
    gsum_kernel<<<dim3(31, 4), 256, 0, s3>>>(4);
    cudaEventRecord(s_evGS[4], s3);

    // ---- level 5 ----
    cudaStreamWaitEvent(0, s_evGS[5], 0);
    seq_kernel<5><<<128, 128>>>(Wh);
    cudaEventRecord(s_evH[5], 0);
    cudaStreamWaitEvent(s2, s_evH[5], 0);
    projR_kernel<<<dim3(16, 4, 2), 256, 0, s2>>>(Wo, out, 5);
    cudaStreamWaitEvent(s3, s_evG0, 0);                     // gsum<3> reads g0_lo G
    cudaStreamWaitEvent(s3, s_evH[5], 0);
    projC_kernel<<<dim3(16, 4, 4), 256, 0, s3>>>(Wh, 5);    // z=0..3
    gsum_kernel<<<dim3(63, 4), 256, 0, s3>>>(3);
    cudaEventRecord(s_evGS[3], s3);

    // ---- level 4 ----
    cudaStreamWaitEvent(0, s_evGS[4], 0);
    seq_kernel<4><<<128, 128>>>(Wh);
    cudaEventRecord(s_evH[4], 0);
    cudaStreamWaitEvent(s2, s_evH[4], 0);
    projR_kernel<<<dim3(32, 4, 2), 256, 0, s2>>>(Wo, out, 4);
    cudaStreamWaitEvent(s3, s_evH[4], 0);
    projC_kernel<<<dim3(32, 4, 3), 256, 0, s3>>>(Wh, 4);    // z=0..2
    gsum_kernel<<<dim3(127, 4), 256, 0, s3>>>(2);
    cudaEventRecord(s_evGS[2], s3);

    // ---- level 3 ----
    cudaStreamWaitEvent(0, s_evGS[3], 0);
    seq_kernel<3><<<128, 128>>>(Wh);
    cudaEventRecord(s_evH[3], 0);
    cudaStreamWaitEvent(s2, s_evH[3], 0);
    projR_kernel<<<dim3(64, 4, 2), 256, 0, s2>>>(Wo, out, 3);
    cudaStreamWaitEvent(s3, s_evH[3], 0);
    projC_kernel<<<dim3(64, 4, 2), 256, 0, s3>>>(Wh, 3);    // z=0..1
    gsum_kernel<<<dim3(255, 4), 256, 0, s3>>>(1);
    cudaEventRecord(s_evGS[1], s3);

    // ---- level 2 ----
    cudaStreamWaitEvent(0, s_evGS[2], 0);
    seq_kernel<2><<<128, 128>>>(Wh);
    cudaEventRecord(s_evH[2], 0);
    cudaStreamWaitEvent(s2, s_evH[2], 0);
    projR_kernel<<<dim3(128, 4, 2), 256, 0, s2>>>(Wo, out, 2);
    cudaStreamWaitEvent(s3, s_evH[2], 0);
    projC_kernel<<<dim3(128, 4, 1), 256, 0, s3>>>(Wh, 2);   // z=0
    gsum_kernel<<<dim3(511, 4), 256, 0, s3>>>(0);
    cudaEventRecord(s_evGS[0], s3);

    // ---- level 1 ---- (no projC: its only consumer stream is JIT in seq<0>)
    cudaStreamWaitEvent(0, s_evGS[1], 0);
    seq_kernel<1><<<128, 128>>>(Wh);
    cudaEventRecord(s_evH[1], 0);
    cudaStreamWaitEvent(s2, s_evH[1], 0);
    projR_kernel<<<dim3(256, 4, 2), 256, 0, s2>>>(Wo, out, 1);

    // ---- level 0 ----
    cudaStreamWaitEvent(0, s_evGS[0], 0);
    seq_kernel<0><<<128, 128>>>(Wh);
    cudaEventRecord(s_evH[0], 0);
    cudaStreamWaitEvent(s2, s_evH[0], 0);
    projR_kernel<<<dim3(512, 4, 2), 256, 0, s2>>>(Wo, out, 0);  // writes Y
    cudaEventRecord(s_evR0, s2);

    finalH_kernel<<<dim3(8, 4), 256>>>(out);
    cudaStreamWaitEvent(0, s_evR0, 0);
}

// round 12
// speedup vs baseline: 1.3272x; 1.3272x over previous
#include <cuda_runtime.h>
#include <cuda_bf16.h>
#include <cstdint>
#include <cstddef>

#define T_STEPS 512
#define B_SZ    256
#define NO_SZ   128

// ---------------------------------------------------------------------------
// Static scratch.
//   g_G   [tile][b][r]   fp32 preacts (gsum folds sources j>=c+2 in place)
//   g_Hep [tile][b][k]   fp32 hidden epochs
//   g_R   [tile][b][o]   prefix-summed output projections
//   g_C   [ctile][b][r]  off-diagonal recurrent projections
// ---------------------------------------------------------------------------
__device__ float g_G  [1020u * 64  * 256];
__device__ float g_Hep[1020u * 64  * 256];
__device__ float g_R  [1020u * 128 * 256];
__device__ float g_C  [988u  * 64  * 256];

__device__ __constant__ int c_S[8] = {0, 0, 256, 512, 704, 832, 912, 960};

__device__ __forceinline__ int hb(int j) { return 1024 - (1024 >> j); }

__device__ __forceinline__ float ftanh(float x) {
    float t = __expf(2.0f * x);
    return 1.0f - __fdividef(2.0f, t + 1.0f);
}

// ---------------------------------------------------------------------------
// bf16 MMA m16n8k16 (row.col, f32 accum)
// ---------------------------------------------------------------------------
__device__ __forceinline__ void mma_bf16(float* d, const uint32_t* a, const uint32_t* b)
{
    asm volatile(
        "mma.sync.aligned.m16n8k16.row.col.f32.bf16.bf16.f32 "
        "{%0,%1,%2,%3},{%4,%5,%6,%7},{%8,%9},{%0,%1,%2,%3};\n"
        : "+f"(d[0]), "+f"(d[1]), "+f"(d[2]), "+f"(d[3])
        : "r"(a[0]), "r"(a[1]), "r"(a[2]), "r"(a[3]), "r"(b[0]), "r"(b[1]));
}

__device__ __forceinline__ uint32_t pack2(float x0, float x1, bool lo)
{
    __nv_bfloat16 h0 = __float2bfloat16(x0);
    __nv_bfloat16 h1 = __float2bfloat16(x1);
    if (lo) {
        h0 = __float2bfloat16(x0 - __bfloat162float(h0));
        h1 = __float2bfloat16(x1 - __bfloat162float(h1));
    }
    __nv_bfloat162 p = __halves2bfloat162(h0, h1);
    return *reinterpret_cast<uint32_t*>(&p);
}

// Shared layout (uint32 words), total 9216 words = 36864 B:
//   AH [64][36] @0   AL [64][36] @2304   BH [64][36] @4608   BL [64][36] @6912
//   S  (float [64][68]) overlays BH/BL region
#define AH_OFF 0
#define AL_OFF 2304
#define BH_OFF 4608
#define BL_OFF 6912

// Stage A (64 rows x 64 k, row-major lda) and B (64 cols x 64 k, k-contig ldb).
// koff applies to BOTH A and B k-indices; pass base (unoffset) pointers.
__device__ __forceinline__ void stage_AB(uint32_t* su,
                                         const float* __restrict__ Ag, int lda, int koff,
                                         const float* __restrict__ Bg, int ldb,
                                         int tid)
{
    for (int idx = tid; idx < 64 * 32; idx += 256) {
        int r = idx >> 5, p = idx & 31;
        float x0 = Ag[(size_t)r * lda + koff + 2 * p];
        float x1 = Ag[(size_t)r * lda + koff + 2 * p + 1];
        su[AH_OFF + r * 36 + p] = pack2(x0, x1, false);
        su[AL_OFF + r * 36 + p] = pack2(x0, x1, true);
    }
    for (int idx = tid; idx < 64 * 16; idx += 256) {
        int c = idx >> 4, q = idx & 15;
        float4 v = *(const float4*)&Bg[(size_t)c * ldb + koff + 4 * q];
        su[BH_OFF + c * 36 + 2 * q]     = pack2(v.x, v.y, false);
        su[BL_OFF + c * 36 + 2 * q]     = pack2(v.x, v.y, true);
        su[BH_OFF + c * 36 + 2 * q + 1] = pack2(v.z, v.w, false);
        su[BL_OFF + c * 36 + 2 * q + 1] = pack2(v.z, v.w, true);
    }
}

// 64x64 tile MMA: warp w -> rows (w&3)*16.., cols (w>>2)*32..; acc[4][4]
__device__ __forceinline__ void mma_block(const uint32_t* su, int warp, int lane,
                                          float (&acc)[4][4])
{
    const int mrow = (warp & 3) * 16;
    const int nb   = (warp >> 2) * 32;
    const int gr   = lane >> 2, tg = lane & 3;
#pragma unroll
    for (int c = 0; c < 4; c++) {
        const int pb = c * 8;
        uint32_t ah[4], al[4];
        ah[0] = su[AH_OFF + (mrow + gr)     * 36 + pb + tg];
        ah[1] = su[AH_OFF + (mrow + gr + 8) * 36 + pb + tg];
        ah[2] = su[AH_OFF + (mrow + gr)     * 36 + pb + 4 + tg];
        ah[3] = su[AH_OFF + (mrow + gr + 8) * 36 + pb + 4 + tg];
        al[0] = su[AL_OFF + (mrow + gr)     * 36 + pb + tg];
        al[1] = su[AL_OFF + (mrow + gr + 8) * 36 + pb + tg];
        al[2] = su[AL_OFF + (mrow + gr)     * 36 + pb + 4 + tg];
        al[3] = su[AL_OFF + (mrow + gr + 8) * 36 + pb + 4 + tg];
#pragma unroll
        for (int nt = 0; nt < 4; nt++) {
            const int colb = nb + nt * 8 + gr;
            uint32_t bh[2], bl[2];
            bh[0] = su[BH_OFF + colb * 36 + pb + tg];
            bh[1] = su[BH_OFF + colb * 36 + pb + 4 + tg];
            bl[0] = su[BL_OFF + colb * 36 + pb + tg];
            bl[1] = su[BL_OFF + colb * 36 + pb + 4 + tg];
            mma_bf16(acc[nt], ah, bh);
            mma_bf16(acc[nt], ah, bl);
            mma_bf16(acc[nt], al, bh);
        }
    }
}

// acc -> S[col][row] transpose staging (S overlays B smem region)
__device__ __forceinline__ void acc_to_S(float* Sf, int warp, int lane, float (&acc)[4][4])
{
    const int mrow = (warp & 3) * 16;
    const int nb   = (warp >> 2) * 32;
    const int gr   = lane >> 2, tg = lane & 3;
#pragma unroll
    for (int nt = 0; nt < 4; nt++) {
        const int c0 = nb + nt * 8 + 2 * tg;
        Sf[(size_t)c0       * 68 + mrow + gr]     = acc[nt][0];
        Sf[(size_t)(c0 + 1) * 68 + mrow + gr]     = acc[nt][1];
        Sf[(size_t)c0       * 68 + mrow + gr + 8] = acc[nt][2];
        Sf[(size_t)(c0 + 1) * 68 + mrow + gr + 8] = acc[nt][3];
    }
}

// ---------------------------------------------------------------------------
// g0: G[c][m] = Wi_c @ x_{m<<c} + (Wi_bias + Wh_bias).
// grid (ntiles, 4), 256 thr; tile index = idx0 + blockIdx.x.
// ---------------------------------------------------------------------------
__global__ void __launch_bounds__(256) g0_kernel(const float* __restrict__ X,
                                                 const float* __restrict__ Wi,
                                                 const float* __restrict__ Wh,
                                                 int idx0)
{
    __shared__ __align__(16) uint32_t su[9216];
    float* Sf = (float*)(su + BH_OFF);

    const int idx = idx0 + blockIdx.x;
    const int v   = 1024 - idx;
    const int c   = __clz(v - 1) - 22;
    const int m   = idx - (1024 - (1024 >> c));
    const int t   = m << c;
    const int b0  = blockIdx.y * 64;
    const int tid = threadIdx.x;
    const int warp = tid >> 5, lane = tid & 31;

    const float* Ag = Wi + (size_t)(c * 64) * 129;
    const float* Bg = X + ((size_t)t * 256 + b0) * 128;

    float acc[4][4];
#pragma unroll
    for (int q = 0; q < 4; q++)
#pragma unroll
        for (int u = 0; u < 4; u++) acc[q][u] = 0.f;

    for (int kh = 0; kh < 2; kh++) {
        stage_AB(su, Ag, 129, kh * 64, Bg, 128, tid);
        __syncthreads();
        mma_block(su, warp, lane, acc);
        __syncthreads();
    }

    {
        const int mrow = (warp & 3) * 16, gr = lane >> 2;
        int r0 = c * 64 + mrow + gr, r1 = r0 + 8;
        float ba = Wi[(size_t)r0 * 129 + 128] + Wh[(size_t)r0 * 513 + 512];
        float bb = Wi[(size_t)r1 * 129 + 128] + Wh[(size_t)r1 * 513 + 512];
#pragma unroll
        for (int nt = 0; nt < 4; nt++) {
            acc[nt][0] += ba; acc[nt][1] += ba;
            acc[nt][2] += bb; acc[nt][3] += bb;
        }
    }

    acc_to_S(Sf, warp, lane, acc);
    __syncthreads();

    float* out = g_G + (size_t)idx * 16384 + (size_t)b0 * 64;
    for (int i = tid; i < 64 * 16; i += 256) {
        int col = i >> 4, rq = i & 15;
        *(float4*)&out[(size_t)col * 64 + rq * 4] = *(float4*)&Sf[(size_t)col * 68 + rq * 4];
    }
}

// ---------------------------------------------------------------------------
// projC: C[z][j][e] = Wh[z-rows, j-cols] @ H_j[e],  z = zbase + blockIdx.z.
// grid (U_j, 4, nz), 256 threads.
// ---------------------------------------------------------------------------
__global__ void __launch_bounds__(256) projC_kernel(const float* __restrict__ Wh,
                                                    int j, int zbase)
{
    __shared__ __align__(16) uint32_t su[9216];
    float* Sf = (float*)(su + BH_OFF);

    const int e   = blockIdx.x;
    const int U   = gridDim.x;
    const int b0  = blockIdx.y * 64;
    const int z   = zbase + blockIdx.z;
    const int tid = threadIdx.x;
    const int warp = tid >> 5, lane = tid & 31;

    const float* Ag = Wh + (size_t)(z * 64) * 513 + j * 64;
    const float* Bg = g_Hep + (size_t)(hb(j) + e) * 16384 + (size_t)b0 * 64;

    float acc[4][4];
#pragma unroll
    for (int q = 0; q < 4; q++)
#pragma unroll
        for (int u = 0; u < 4; u++) acc[q][u] = 0.f;

    stage_AB(su, Ag, 513, 0, Bg, 64, tid);
    __syncthreads();
    mma_block(su, warp, lane, acc);
    __syncthreads();
    acc_to_S(Sf, warp, lane, acc);
    __syncthreads();

    float* out = g_C + (size_t)(c_S[j] + z * U + e) * 16384 + (size_t)b0 * 64;
    for (int i = tid; i < 64 * 16; i += 256) {
        int col = i >> 4, rq = i & 15;
        *(float4*)&out[(size_t)col * 64 + rq * 4] =
            *(float4*)&Sf[(size_t)col * 68 + rq * 4];
    }
}

// ---------------------------------------------------------------------------
// gsum: G'[m] = G[m] + sum_{j in [jlo, jhi)} C[C][j][(m-1)>>(j-C)]  (m >= 1)
// Phase-splittable: level C's full source set is [C+2, 8).
// ---------------------------------------------------------------------------
__global__ void __launch_bounds__(256) gsum_kernel(int C, int jlo, int jhi)
{
    const int m   = blockIdx.x + 1;
    const int b0  = blockIdx.y * 64;
    const int tid = threadIdx.x;
    const int HB  = 1024 - (1024 >> C);

    float* Gt = g_G + (size_t)(HB + m) * 16384 + (size_t)b0 * 64;

    const float* Ct[6];
    int ns = 0;
    for (int j = jlo; j < jhi; j++) {
        int e = (m - 1) >> (j - C);
        Ct[ns++] = g_C + (size_t)(c_S[j] + C * (512 >> j) + e) * 16384 + (size_t)b0 * 64;
    }

    for (int i = tid; i < 1024; i += 256) {
        float4 a = *(float4*)&Gt[i * 4];
        for (int s = 0; s < ns; s++) {
            float4 v = *(const float4*)&Ct[s][i * 4];
            a.x += v.x; a.y += v.y; a.z += v.z; a.w += v.w;
        }
        *(float4*)&Gt[i * 4] = a;
    }
}

// ---------------------------------------------------------------------------
// projR: R_j[e] rows z*64.. = Wo[rows, j-cols] @ H_j[e] + R_{j+1}[e>>1]
//        (+Wo bias at j=7; tanh->Y at j=0).
// ---------------------------------------------------------------------------
__global__ void __launch_bounds__(256) projR_kernel(const float* __restrict__ Wo,
                                                    float* __restrict__ Y, int j)
{
    __shared__ __align__(16) uint32_t su[9216];
    float* Sf = (float*)(su + BH_OFF);

    const int e   = blockIdx.x;
    const int b0  = blockIdx.y * 64;
    const int z   = blockIdx.z;
    const int tid = threadIdx.x;
    const int warp = tid >> 5, lane = tid & 31;

    const float* Ag = Wo + (size_t)(z * 64) * 513 + j * 64;
    const float* Bg = g_Hep + (size_t)(hb(j) + e) * 16384 + (size_t)b0 * 64;

    float acc[4][4];
#pragma unroll
    for (int q = 0; q < 4; q++)
#pragma unroll
        for (int u = 0; u < 4; u++) acc[q][u] = 0.f;

    stage_AB(su, Ag, 513, 0, Bg, 64, tid);
    __syncthreads();
    mma_block(su, warp, lane, acc);
    __syncthreads();
    acc_to_S(Sf, warp, lane, acc);
    __syncthreads();

    const int o0 = z * 64;
    const float* Rpar = (j < 7)
        ? g_R + (size_t)(hb(j + 1) + (e >> 1)) * 32768
        : nullptr;
    for (int i = tid; i < 64 * 16; i += 256) {
        int col = i >> 4, rq = i & 15;
        float4 s = *(float4*)&Sf[(size_t)col * 68 + rq * 4];
        if (j < 7) {
            float4 p = *(const float4*)&Rpar[(size_t)(b0 + col) * 128 + o0 + rq * 4];
            s.x += p.x; s.y += p.y; s.z += p.z; s.w += p.w;
        } else {
            s.x += Wo[(size_t)(o0 + rq * 4 + 0) * 513 + 512];
            s.y += Wo[(size_t)(o0 + rq * 4 + 1) * 513 + 512];
            s.z += Wo[(size_t)(o0 + rq * 4 + 2) * 513 + 512];
            s.w += Wo[(size_t)(o0 + rq * 4 + 3) * 513 + 512];
        }
        if (j == 0) {
            float4 y = make_float4(ftanh(s.x), ftanh(s.y), ftanh(s.z), ftanh(s.w));
            *(float4*)&Y[((size_t)e * 256 + b0 + col) * 128 + o0 + rq * 4] = y;
        } else {
            *(float4*)&g_R[(size_t)(hb(j) + e) * 32768 +
                           (size_t)(b0 + col) * 128 + o0 + rq * 4] = s;
        }
    }
}

// ---------------------------------------------------------------------------
// seq<C>: H[m] = tanh(G'[m] + C1[(m-1)>>1] + W_CC @ H[m-1])
// (G' already folds all C streams with s>=2 via gsum.)
// grid 128 CTAs x 2 batch cols, 128 threads; prefetch depth 8.
// ---------------------------------------------------------------------------
template <int C>
__global__ void __launch_bounds__(128) seq_kernel(const float* __restrict__ Wh)
{
    constexpr int  U    = 512 >> C;
    constexpr bool HASC = (C < 7);
    constexpr int  HB   = 1024 - (1024 >> C);
    constexpr int  csl[8] = {0, 0, 256, 512, 704, 832, 912, 960};
    constexpr int  C1B  = HASC ? (csl[C + 1] + C * (512 >> (C + 1))) : 0;
    constexpr int  D    = (U < 8) ? U : 8;

    const int tid = threadIdx.x;
    const int lb  = tid >> 6;
    const int r   = tid & 63;
    const int b   = blockIdx.x * 2 + lb;
    const int off = b * 64 + r;

    __shared__ float Ws[64][65];
    __shared__ float Hs[2][2][64];

    for (int i = tid; i < 4096; i += 128)
        Ws[i >> 6][i & 63] = Wh[(size_t)(C * 64 + (i >> 6)) * 513 + C * 64 + (i & 63)];
    __syncthreads();

    float w[64];
#pragma unroll
    for (int q = 0; q < 64; q++) w[q] = Ws[r][q];

    const float* Gb  = g_G + (size_t)HB * 16384;
    const float* Cb  = g_C + (size_t)C1B * 16384;
    float*       Hbp = g_Hep + (size_t)HB * 16384;

    float gv[D], cv[D];
#pragma unroll
    for (int i = 0; i < D; i++) {
        gv[i] = Gb[(size_t)i * 16384 + off];
        cv[i] = 0.f;
        if (HASC && i >= 1) cv[i] = Cb[(size_t)((i - 1) >> 1) * 16384 + off];
    }

    for (int m0 = 0; m0 < U; m0 += D) {
#pragma unroll
        for (int i = 0; i < D; i++) {
            const int m  = m0 + i;
            const int rb = m & 1;
            float a = gv[i];
            if (m > 0) {
                float a0 = 0.f, a1 = 0.f, a2 = 0.f, a3 = 0.f;
#pragma unroll
                for (int q = 0; q < 64; q += 4) {
                    float4 hv = *(const float4*)&Hs[rb][lb][q];
                    a0 += w[q + 0] * hv.x;
                    a1 += w[q + 1] * hv.y;
                    a2 += w[q + 2] * hv.z;
                    a3 += w[q + 3] * hv.w;
                }
                a += (a0 + a1) + (a2 + a3);
                if (HASC) a += cv[i];
            }
            float h = ftanh(a);
            Hbp[(size_t)m * 16384 + off] = h;
            Hs[rb ^ 1][lb][r] = h;
            const int mf = m + D;
            if (mf < U) {
                gv[i] = Gb[(size_t)mf * 16384 + off];
                if (HASC) cv[i] = Cb[(size_t)((mf - 1) >> 1) * 16384 + off];
            }
            __syncthreads();
        }
    }
}

// ---------------------------------------------------------------------------
// final H: out[T*B*NO + (j*64+r)*256 + b] = H_j[last epoch][b][r] (transpose)
// ---------------------------------------------------------------------------
__global__ void __launch_bounds__(256) finalH_kernel(float* __restrict__ out)
{
    __shared__ float S[64][65];
    const int j   = blockIdx.x;
    const int b0  = blockIdx.y * 64;
    const int tid = threadIdx.x;
    const int e   = (512 >> j) - 1;
    const float* Hj = g_Hep + (size_t)(hb(j) + e) * 16384;

    for (int i = tid; i < 4096; i += 256) {
        int rr = i & 63, bb = i >> 6;
        S[bb][rr] = Hj[(size_t)(b0 + bb) * 64 + rr];
    }
    __syncthreads();
    for (int i = tid; i < 4096; i += 256) {
        int bb = i & 63, rr = i >> 6;
        out[(size_t)T_STEPS * B_SZ * NO_SZ + (size_t)(j * 64 + rr) * 256 + b0 + bb] =
            S[bb][rr];
    }
}

// ---------------------------------------------------------------------------
// Launch (R9 structure; gsum for levels 0/1 split into two phases).
//   main: g0_hi -> seq<j> -> projC(urgent z=j-1) -> ...
//   s1  : g0_lo (levels 3..0)
//   s2  : projR chain (R_7..R_0 -> Y), join at end
//   s3  : projC deferred + gsum phases; seq<C> gates on evGS[C]
// ---------------------------------------------------------------------------
static cudaStream_t s_s1 = nullptr, s_s2 = nullptr, s_s3 = nullptr;
static cudaEvent_t  s_ev0, s_evG0, s_evH[8], s_evR0, s_evGS[6];
static int s_state = 0;

static bool ensure_streams()
{
    if (s_state) return s_state > 0;
    bool ok = true;
    ok &= cudaStreamCreateWithFlags(&s_s1, cudaStreamNonBlocking) == cudaSuccess;
    ok &= cudaStreamCreateWithFlags(&s_s2, cudaStreamNonBlocking) == cudaSuccess;
    ok &= cudaStreamCreateWithFlags(&s_s3, cudaStreamNonBlocking) == cudaSuccess;
    ok &= cudaEventCreateWithFlags(&s_ev0,  cudaEventDisableTiming) == cudaSuccess;
    ok &= cudaEventCreateWithFlags(&s_evG0, cudaEventDisableTiming) == cudaSuccess;
    ok &= cudaEventCreateWithFlags(&s_evR0, cudaEventDisableTiming) == cudaSuccess;
    for (int i = 0; i < 8; i++)
        ok &= cudaEventCreateWithFlags(&s_evH[i], cudaEventDisableTiming) == cudaSuccess;
    for (int i = 0; i < 6; i++)
        ok &= cudaEventCreateWithFlags(&s_evGS[i], cudaEventDisableTiming) == cudaSuccess;
    s_state = ok ? 1 : -1;
    return ok;
}

extern "C" void kernel_launch(void* const* d_in, const int* in_sizes, int n_in,
                              void* d_out, int out_size)
{
    const float* X  = nullptr;
    const float* Wi = nullptr;
    const float* Wh = nullptr;
    const float* Wo = nullptr;
    for (int i = 0; i < n_in; i++) {
        switch (in_sizes[i]) {
            case 512 * 256 * 128: X  = (const float*)d_in[i]; break;
            case 512 * 129:       Wi = (const float*)d_in[i]; break;
            case 512 * 513:       Wh = (const float*)d_in[i]; break;
            case 128 * 513:       Wo = (const float*)d_in[i]; break;
            default: break;
        }
    }
    float* out = (float*)d_out;

    if (!ensure_streams()) {
        // -------- Fallback: single-stream chain ----------------------------
        g0_kernel<<<dim3(1020, 4), 256>>>(X, Wi, Wh, 0);
        seq_kernel<7><<<128, 128>>>(Wh);
        projR_kernel<<<dim3(4, 4, 2), 256>>>(Wo, out, 7);
        projC_kernel<<<dim3(4, 4, 7), 256>>>(Wh, 7, 0);
        seq_kernel<6><<<128, 128>>>(Wh);
        projR_kernel<<<dim3(8, 4, 2), 256>>>(Wo, out, 6);
        projC_kernel<<<dim3(8, 4, 6), 256>>>(Wh, 6, 0);
        gsum_kernel<<<dim3(15, 4), 256>>>(5, 7, 8);
        seq_kernel<5><<<128, 128>>>(Wh);
        projR_kernel<<<dim3(16, 4, 2), 256>>>(Wo, out, 5);
        projC_kernel<<<dim3(16, 4, 5), 256>>>(Wh, 5, 0);
        gsum_kernel<<<dim3(31, 4), 256>>>(4, 6, 8);
        seq_kernel<4><<<128, 128>>>(Wh);
        projR_kernel<<<dim3(32, 4, 2), 256>>>(Wo, out, 4);
        projC_kernel<<<dim3(32, 4, 4), 256>>>(Wh, 4, 0);
        gsum_kernel<<<dim3(63, 4), 256>>>(3, 5, 8);
        seq_kernel<3><<<128, 128>>>(Wh);
        projR_kernel<<<dim3(64, 4, 2), 256>>>(Wo, out, 3);
        projC_kernel<<<dim3(64, 4, 3), 256>>>(Wh, 3, 0);
        gsum_kernel<<<dim3(127, 4), 256>>>(2, 4, 8);
        seq_kernel<2><<<128, 128>>>(Wh);
        projR_kernel<<<dim3(128, 4, 2), 256>>>(Wo, out, 2);
        projC_kernel<<<dim3(128, 4, 2), 256>>>(Wh, 2, 0);
        gsum_kernel<<<dim3(255, 4), 256>>>(1, 3, 8);
        seq_kernel<1><<<128, 128>>>(Wh);
        projR_kernel<<<dim3(256, 4, 2), 256>>>(Wo, out, 1);
        projC_kernel<<<dim3(256, 4, 1), 256>>>(Wh, 1, 0);
        gsum_kernel<<<dim3(511, 4), 256>>>(0, 2, 8);
        seq_kernel<0><<<128, 128>>>(Wh);
        projR_kernel<<<dim3(512, 4, 2), 256>>>(Wo, out, 0);
        finalH_kernel<<<dim3(8, 4), 256>>>(out);
        return;
    }

    cudaStream_t s1 = s_s1, s2 = s_s2, s3 = s_s3;

    // Fork: g0_lo (levels 3..0, tiles 0..959) on s1.
    cudaEventRecord(s_ev0, 0);
    cudaStreamWaitEvent(s1, s_ev0, 0);
    g0_kernel<<<dim3(960, 4), 256, 0, s1>>>(X, Wi, Wh, 0);
    cudaEventRecord(s_evG0, s1);

    // Main: g0_hi (levels 7..4, tiles 960..1019).
    g0_kernel<<<dim3(60, 4), 256>>>(X, Wi, Wh, 960);

    // ---- level 7 ----
    seq_kernel<7><<<128, 128>>>(Wh);
    cudaEventRecord(s_evH[7], 0);
    cudaStreamWaitEvent(s2, s_evH[7], 0);
    projR_kernel<<<dim3(4, 4, 2), 256, 0, s2>>>(Wo, out, 7);
    cudaStreamWaitEvent(s3, s_evH[7], 0);
    projC_kernel<<<dim3(4, 4, 6), 256, 0, s3>>>(Wh, 7, 0);   // deferred z=0..5
    gsum_kernel<<<dim3(15, 4), 256, 0, s3>>>(5, 7, 8);
    cudaEventRecord(s_evGS[5], s3);
    projC_kernel<<<dim3(4, 4, 1), 256>>>(Wh, 7, 6);          // urgent z=6

    // ---- level 6 ----
    seq_kernel<6><<<128, 128>>>(Wh);
    cudaEventRecord(s_evH[6], 0);
    cudaStreamWaitEvent(s2, s_evH[6], 0);
    projR_kernel<<<dim3(8, 4, 2), 256, 0, s2>>>(Wo, out, 6);
    cudaStreamWaitEvent(s3, s_evH[6], 0);
    projC_kernel<<<dim3(8, 4, 5), 256, 0, s3>>>(Wh, 6, 0);   // deferred z=0..4
    gsum_kernel<<<dim3(31, 4), 256, 0, s3>>>(4, 6, 8);
    cudaEventRecord(s_evGS[4], s3);
    projC_kernel<<<dim3(8, 4, 1), 256>>>(Wh, 6, 5);          // urgent z=5

    // ---- level 5 ----
    cudaStreamWaitEvent(0, s_evGS[5], 0);
    seq_kernel<5><<<128, 128>>>(Wh);
    cudaEventRecord(s_evH[5], 0);
    cudaStreamWaitEvent(s2, s_evH[5], 0);
    projR_kernel<<<dim3(16, 4, 2), 256, 0, s2>>>(Wo, out, 5);
    cudaStreamWaitEvent(s3, s_evG0, 0);                      // gsum<3> reads g0_lo G
    cudaStreamWaitEvent(s3, s_evH[5], 0);
    projC_kernel<<<dim3(16, 4, 4), 256, 0, s3>>>(Wh, 5, 0);  // deferred z=0..3
    gsum_kernel<<<dim3(63, 4), 256, 0, s3>>>(3, 5, 8);
    cudaEventRecord(s_evGS[3], s3);
    projC_kernel<<<dim3(16, 4, 1), 256>>>(Wh, 5, 4);         // urgent z=4

    // ---- level 4 ----
    cudaStreamWaitEvent(0, s_evGS[4], 0);
    seq_kernel<4><<<128, 128>>>(Wh);
    cudaEventRecord(s_evH[4], 0);
    cudaStreamWaitEvent(s2, s_evH[4], 0);
    projR_kernel<<<dim3(32, 4, 2), 256, 0, s2>>>(Wo, out, 4);
    cudaStreamWaitEvent(s3, s_evH[4], 0);
    projC_kernel<<<dim3(32, 4, 3), 256, 0, s3>>>(Wh, 4, 0);  // deferred z=0..2
    gsum_kernel<<<dim3(127, 4), 256, 0, s3>>>(2, 4, 8);
    cudaEventRecord(s_evGS[2], s3);
    gsum_kernel<<<dim3(255, 4), 256, 0, s3>>>(1, 4, 8);      // gsum<1> phase A
    projC_kernel<<<dim3(32, 4, 1), 256>>>(Wh, 4, 3);         // urgent z=3

    // ---- level 3 ----
    cudaStreamWaitEvent(0, s_evGS[3], 0);
    seq_kernel<3><<<128, 128>>>(Wh);
    cudaEventRecord(s_evH[3], 0);
    cudaStreamWaitEvent(s2, s_evH[3], 0);
    projR_kernel<<<dim3(64, 4, 2), 256, 0, s2>>>(Wo, out, 3);
    cudaStreamWaitEvent(s3, s_evH[3], 0);
    projC_kernel<<<dim3(64, 4, 2), 256, 0, s3>>>(Wh, 3, 0);  // deferred z=0..1
    gsum_kernel<<<dim3(255, 4), 256, 0, s3>>>(1, 3, 4);      // gsum<1> phase B
    cudaEventRecord(s_evGS[1], s3);
    gsum_kernel<<<dim3(511, 4), 256, 0, s3>>>(0, 3, 8);      // gsum<0> phase A
    projC_kernel<<<dim3(64, 4, 1), 256>>>(Wh, 3, 2);         // urgent z=2

    // ---- level 2 ----
    cudaStreamWaitEvent(0, s_evGS[2], 0);
    seq_kernel<2><<<128, 128>>>(Wh);
    cudaEventRecord(s_evH[2], 0);
    cudaStreamWaitEvent(s2, s_evH[2], 0);
    projR_kernel<<<dim3(128, 4, 2), 256, 0, s2>>>(Wo, out, 2);
    cudaStreamWaitEvent(s3, s_evH[2], 0);
    projC_kernel<<<dim3(128, 4, 1), 256, 0, s3>>>(Wh, 2, 0); // deferred z=0
    gsum_kernel<<<dim3(511, 4), 256, 0, s3>>>(0, 2, 3);      // gsum<0> phase B
    cudaEventRecord(s_evGS[0], s3);
    projC_kernel<<<dim3(128, 4, 1), 256>>>(Wh, 2, 1);        // urgent z=1

    // ---- level 1 ----
    cudaStreamWaitEvent(0, s_evGS[1], 0);
    seq_kernel<1><<<128, 128>>>(Wh);
    cudaEventRecord(s_evH[1], 0);
    cudaStreamWaitEvent(s2, s_evH[1], 0);
    projR_kernel<<<dim3(256, 4, 2), 256, 0, s2>>>(Wo, out, 1);
    projC_kernel<<<dim3(256, 4, 1), 256>>>(Wh, 1, 0);        // urgent z=0

    // ---- level 0 ----
    cudaStreamWaitEvent(0, s_evGS[0], 0);
    seq_kernel<0><<<128, 128>>>(Wh);
    cudaEventRecord(s_evH[0], 0);
    cudaStreamWaitEvent(s2, s_evH[0], 0);
    projR_kernel<<<dim3(512, 4, 2), 256, 0, s2>>>(Wo, out, 0);  // writes Y
    cudaEventRecord(s_evR0, s2);

    finalH_kernel<<<dim3(8, 4), 256>>>(out);
    cudaStreamWaitEvent(0, s_evR0, 0);
}